// round 1
// baseline (speedup 1.0000x reference)
#include <cuda_runtime.h>
#include <math.h>

#define NV 2048
#define VV 4096           // 2*NV
#define BB 4
#define C0 64
#define HD 128
#define CH 512            // BB*HD
#define EE (5*NV)         // 10240 edges
#define NNZ (46*NV)       // 94208 memberships

// ---------------- scratch (device globals; no allocation) ----------------
__device__ float g_f1[NV*C0];
__device__ float g_f2[NV*C0];
__device__ int   g_knn1[NV*19];
__device__ int   g_knn2[NV*13];
__device__ int   g_dv[VV];
__device__ float g_isdv[VV];
__device__ int   g_off[VV+1];
__device__ int   g_ctr[VV];
__device__ int   g_adj[NNZ];
__device__ float g_x[VV*CH];   // linear output (xW)
__device__ float g_z[EE*CH];   // edge features
__device__ float g_y[VV*CH];   // layer-1 output

// ---------------- kernels ----------------

__global__ void k_zero() {
    int i = blockIdx.x * blockDim.x + threadIdx.x;
    if (i < VV) g_dv[i] = 0;
}

// batch-mean + L2-normalize rows for both modalities. grid VV, block 64.
__global__ void k_meannorm(const float* __restrict__ f1, const float* __restrict__ f2) {
    int v = blockIdx.x;
    int c = threadIdx.x;
    const float* src; float* dst; int n;
    if (v < NV) { src = f1; dst = g_f1; n = v; }
    else        { src = f2; dst = g_f2; n = v - NV; }
    float m = 0.f;
#pragma unroll
    for (int b = 0; b < BB; b++) m += src[(b*NV + n)*C0 + c];
    m *= (1.0f / BB);
    __shared__ float red[64];
    red[c] = m*m;
    __syncthreads();
    for (int s = 32; s > 0; s >>= 1) {
        if (c < s) red[c] += red[c+s];
        __syncthreads();
    }
    float norm = sqrtf(red[0]);
    float d = fmaxf(norm, 1e-12f);
    dst[n*C0 + c] = m / d;
}

// cosine sim + top-K per row (K includes self). 4 rows per block, block 256.
__global__ void k_topk(int modal) {
    const float* __restrict__ f = modal ? g_f2 : g_f1;
    int* knn = modal ? g_knn2 : g_knn1;
    const int K = modal ? 13 : 19;

    __shared__ float sf[4][C0];
    __shared__ float sim[4][NV];
    __shared__ float rv[256];
    __shared__ int   ri[256];

    int tid = threadIdx.x;
    int r0 = blockIdx.x * 4;

    for (int i = tid; i < 4*C0; i += 256)
        sf[i >> 6][i & 63] = f[(r0 + (i >> 6))*C0 + (i & 63)];
    __syncthreads();

    for (int j = tid; j < NV; j += 256) {
        const float4* fj = (const float4*)(f + j*C0);
        float a0=0,a1=0,a2=0,a3=0;
#pragma unroll
        for (int q = 0; q < C0/4; q++) {
            float4 x = fj[q];
            int c = q*4;
            a0 += x.x*sf[0][c] + x.y*sf[0][c+1] + x.z*sf[0][c+2] + x.w*sf[0][c+3];
            a1 += x.x*sf[1][c] + x.y*sf[1][c+1] + x.z*sf[1][c+2] + x.w*sf[1][c+3];
            a2 += x.x*sf[2][c] + x.y*sf[2][c+1] + x.z*sf[2][c+2] + x.w*sf[2][c+3];
            a3 += x.x*sf[3][c] + x.y*sf[3][c+1] + x.z*sf[3][c+2] + x.w*sf[3][c+3];
        }
        sim[0][j]=a0; sim[1][j]=a1; sim[2][j]=a2; sim[3][j]=a3;
    }
    __syncthreads();

    for (int r = 0; r < 4; r++) {
        for (int it = 0; it < K; it++) {
            float bv = -1e30f; int bi = NV;
            for (int j = tid; j < NV; j += 256) {
                float v = sim[r][j];
                if (v > bv) { bv = v; bi = j; }   // strict > keeps lowest index
            }
            rv[tid] = bv; ri[tid] = bi;
            __syncthreads();
            for (int s = 128; s > 0; s >>= 1) {
                if (tid < s) {
                    float ov = rv[tid+s]; int oi = ri[tid+s];
                    if (ov > rv[tid] || (ov == rv[tid] && oi < ri[tid])) {
                        rv[tid] = ov; ri[tid] = oi;
                    }
                }
                __syncthreads();
            }
            if (tid == 0) { knn[(r0+r)*K + it] = ri[0]; sim[r][ri[0]] = -1e30f; }
            __syncthreads();
        }
    }
}

// count vertex degrees over the 4 knn edge blocks (inter edges add +1 in scan)
__global__ void k_count() {
    int idx = blockIdx.x * blockDim.x + threadIdx.x;
    if (idx >= NV*44) return;
    int j = idx / 44, t = idx % 44;
    int v;
    if      (t < 7)  v = g_knn1[j*19 + t];
    else if (t < 26) v = g_knn1[j*19 + t - 7];
    else if (t < 31) v = NV + g_knn2[j*13 + t - 26];
    else             v = NV + g_knn2[j*13 + t - 31];
    atomicAdd(&g_dv[v], 1);
}

// single-block scan of (dv+1) -> offsets; also invsqrt(DV) and counter reset
__global__ void k_scan() {
    __shared__ int part[1024];
    int tid = threadIdx.x;
    int base = tid * 4;
    int loc[4]; int s = 0;
#pragma unroll
    for (int i = 0; i < 4; i++) {
        int d = g_dv[base+i] + 1;     // +1 for the inter edge
        loc[i] = d; s += d;
        g_isdv[base+i] = rsqrtf((float)d);
        g_ctr[base+i] = 0;
    }
    part[tid] = s;
    __syncthreads();
    for (int d = 1; d < 1024; d <<= 1) {
        int t = (tid >= d) ? part[tid-d] : 0;
        __syncthreads();
        part[tid] += t;
        __syncthreads();
    }
    int run = part[tid] - s;
#pragma unroll
    for (int i = 0; i < 4; i++) { g_off[base+i] = run; run += loc[i]; }
    if (tid == 1023) g_off[VV] = part[1023];
}

// fill vertex->edge adjacency
__global__ void k_fill() {
    int idx = blockIdx.x * blockDim.x + threadIdx.x;
    if (idx >= NV*46) return;
    int v, e;
    if (idx < NV*44) {
        int j = idx / 44, t = idx % 44;
        if      (t < 7)  { v = g_knn1[j*19 + t];           e = j; }
        else if (t < 26) { v = g_knn1[j*19 + t - 7];       e = NV + j; }
        else if (t < 31) { v = NV + g_knn2[j*13 + t - 26]; e = 2*NV + j; }
        else             { v = NV + g_knn2[j*13 + t - 31]; e = 3*NV + j; }
    } else {
        int r = idx - NV*44;          // 0..2NV-1
        v = r;
        e = 4*NV + (r & (NV-1));
    }
    int slot = atomicAdd(&g_ctr[v], 1);
    g_adj[g_off[v] + slot] = e;
}

// layer-1 linear: xw[v][b*HD+o] = sum_f in[b][v][f]*W1[o][f]
__global__ void k_lin1(const float* __restrict__ f1, const float* __restrict__ f2,
                       const float* __restrict__ W) {
    __shared__ float Ws[128][65];
    __shared__ float xs[8][64];
    int o = threadIdx.x;           // 0..127
    int b = blockIdx.y;
    int v0 = blockIdx.x * 8;
    for (int i = o; i < 128*64; i += 128) Ws[i >> 6][i & 63] = W[i];
    for (int i = o; i < 8*64; i += 128) {
        int v = v0 + (i >> 6), fc = i & 63;
        xs[i >> 6][fc] = (v < NV) ? f1[(b*NV + v)*C0 + fc]
                                  : f2[(b*NV + v - NV)*C0 + fc];
    }
    __syncthreads();
#pragma unroll
    for (int vi = 0; vi < 8; vi++) {
        float acc = 0.f;
#pragma unroll
        for (int f = 0; f < 64; f++) acc += xs[vi][f] * Ws[o][f];
        g_x[(v0+vi)*CH + b*HD + o] = acc;
    }
}

// layer-2 linear: reads g_y, Fin=128 (two 64-wide halves)
__global__ void k_lin2(const float* __restrict__ W) {
    __shared__ float Ws[128][65];
    __shared__ float xs[8][64];
    int o = threadIdx.x;
    int b = blockIdx.y;
    int v0 = blockIdx.x * 8;
    float acc[8];
#pragma unroll
    for (int vi = 0; vi < 8; vi++) acc[vi] = 0.f;
    for (int half = 0; half < 2; half++) {
        __syncthreads();
        for (int i = o; i < 128*64; i += 128) {
            int r = i >> 6, fc = i & 63;
            Ws[r][fc] = W[r*128 + half*64 + fc];
        }
        for (int i = o; i < 8*64; i += 128) {
            int vi = i >> 6, fc = i & 63;
            xs[vi][fc] = g_y[(v0+vi)*CH + b*HD + half*64 + fc];
        }
        __syncthreads();
#pragma unroll
        for (int vi = 0; vi < 8; vi++) {
            float a = 0.f;
#pragma unroll
            for (int f = 0; f < 64; f++) a += xs[vi][f] * Ws[o][f];
            acc[vi] += a;
        }
    }
#pragma unroll
    for (int vi = 0; vi < 8; vi++)
        g_x[(v0+vi)*CH + b*HD + o] = acc[vi];
}

// edge gather: z[e] = (1/DE^2) * sum_{u in e} isdv[u] * x[u]
__global__ void k_edge() {
    __shared__ int   mem[19];
    __shared__ float sw[19];
    int e = blockIdx.x;
    int tid = threadIdx.x;          // 256 threads, 2 channels each
    int blk = e >> 11;
    int j = e & (NV-1);
    int cnt;
    if      (blk == 0) cnt = 7;
    else if (blk == 1) cnt = 19;
    else if (blk == 2) cnt = 5;
    else if (blk == 3) cnt = 13;
    else               cnt = 2;
    float w = 1.f / ((float)cnt * (float)cnt);
    if (tid < cnt) {
        int u;
        if      (blk <= 1) u = g_knn1[j*19 + tid];
        else if (blk <= 3) u = NV + g_knn2[j*13 + tid];
        else               u = (tid == 0) ? j : NV + j;
        mem[tid] = u;
        sw[tid] = g_isdv[u];
    }
    __syncthreads();
    float a0 = 0.f, a1 = 0.f;
    for (int t = 0; t < cnt; t++) {
        const float* xr = g_x + mem[t]*CH;
        float s = sw[t];
        a0 += xr[tid]       * s;
        a1 += xr[tid + 256] * s;
    }
    g_z[e*CH + tid]       = w * a0;
    g_z[e*CH + tid + 256] = w * a1;
}

// vertex gather + relu. mode 0 -> g_y, mode 1 -> d_out (permuted layout)
__global__ void k_vert(float* __restrict__ out, int mode) {
    int v = blockIdx.x;
    int tid = threadIdx.x;          // 256 threads, 2 channels each
    int o0 = g_off[v], o1 = g_off[v+1];
    float a0 = 0.f, a1 = 0.f;
    for (int i = o0; i < o1; i++) {
        int e = g_adj[i];
        const float* zr = g_z + e*CH;
        a0 += zr[tid];
        a1 += zr[tid + 256];
    }
    float s = g_isdv[v];
    a0 = fmaxf(a0 * s, 0.f);
    a1 = fmaxf(a1 * s, 0.f);
    if (mode == 0) {
        g_y[v*CH + tid]       = a0;
        g_y[v*CH + tid + 256] = a1;
    } else {
        int h = (v >= NV) ? 1 : 0;
        int n = v - h*NV;
        int c0 = tid, c1 = tid + 256;
        out[((h*BB + (c0 >> 7))*NV + n)*HD + (c0 & 127)] = a0;
        out[((h*BB + (c1 >> 7))*NV + n)*HD + (c1 & 127)] = a1;
    }
}

// ---------------- launch ----------------
extern "C" void kernel_launch(void* const* d_in, const int* in_sizes, int n_in,
                              void* d_out, int out_size) {
    const float* f1 = (const float*)d_in[0];
    const float* f2 = (const float*)d_in[1];
    const float* W1 = (const float*)d_in[2];
    const float* W2 = (const float*)d_in[3];
    float* out = (float*)d_out;

    k_zero<<<(VV + 255)/256, 256>>>();
    k_meannorm<<<VV, 64>>>(f1, f2);
    k_topk<<<NV/4, 256>>>(0);
    k_topk<<<NV/4, 256>>>(1);
    k_count<<<(NV*44 + 255)/256, 256>>>();
    k_scan<<<1, 1024>>>();
    k_fill<<<(NV*46 + 255)/256, 256>>>();

    // layer 1
    k_lin1<<<dim3(VV/8, BB), 128>>>(f1, f2, W1);
    k_edge<<<EE, 256>>>();
    k_vert<<<VV, 256>>>(out, 0);

    // layer 2
    k_lin2<<<dim3(VV/8, BB), 128>>>(W2);
    k_edge<<<EE, 256>>>();
    k_vert<<<VV, 256>>>(out, 1);
}

// round 2
// speedup vs baseline: 3.2695x; 3.2695x over previous
#include <cuda_runtime.h>
#include <math.h>

#define NV 2048
#define VV 4096           // 2*NV
#define BB 4
#define C0 64
#define HD 128
#define CH 512            // BB*HD
#define EE (5*NV)         // 10240 edges
#define NNZ (46*NV)       // 94208 memberships

// ---------------- scratch (device globals; no allocation) ----------------
__device__ float g_f1[NV*C0];
__device__ float g_f2[NV*C0];
__device__ float g_sim[2][NV*NV];
__device__ int   g_knn1[NV*19];
__device__ int   g_knn2[NV*13];
__device__ int   g_dv[VV];
__device__ float g_isdv[VV];
__device__ int   g_off[VV+1];
__device__ int   g_ctr[VV];
__device__ int   g_adj[NNZ];
__device__ float g_x[VV*CH];   // linear output (xW)
__device__ float g_z[EE*CH];   // edge features
__device__ float g_y[VV*CH];   // layer-1 output

// ---------------- kernels ----------------

__global__ void k_zero() {
    int i = blockIdx.x * blockDim.x + threadIdx.x;
    if (i < VV) g_dv[i] = 0;
}

// batch-mean + L2-normalize rows for both modalities. grid VV, block 64.
__global__ void k_meannorm(const float* __restrict__ f1, const float* __restrict__ f2) {
    int v = blockIdx.x;
    int c = threadIdx.x;
    const float* src; float* dst; int n;
    if (v < NV) { src = f1; dst = g_f1; n = v; }
    else        { src = f2; dst = g_f2; n = v - NV; }
    float m = 0.f;
#pragma unroll
    for (int b = 0; b < BB; b++) m += src[(b*NV + n)*C0 + c];
    m *= (1.0f / BB);
    __shared__ float red[64];
    red[c] = m*m;
    __syncthreads();
    for (int s = 32; s > 0; s >>= 1) {
        if (c < s) red[c] += red[c+s];
        __syncthreads();
    }
    float norm = sqrtf(red[0]);
    float d = fmaxf(norm, 1e-12f);
    dst[n*C0 + c] = m / d;
}

// sim = F @ F^T, tiled 64x64, K=64 resident in smem. grid (32,32,2), block 256.
__global__ void k_sim() {
    int modal = blockIdx.z;
    const float* __restrict__ f = modal ? g_f2 : g_f1;
    float* __restrict__ S = g_sim[modal];
    __shared__ float As[64][65];
    __shared__ float Bs[64][65];
    int tx = threadIdx.x;
    int r0 = blockIdx.y * 64, c0 = blockIdx.x * 64;
    for (int i = tx; i < 64*64; i += 256) {
        int r = i >> 6, c = i & 63;
        As[r][c] = f[(r0 + r)*C0 + c];
        Bs[r][c] = f[(c0 + r)*C0 + c];
    }
    __syncthreads();
    int ty = tx >> 4, tcc = tx & 15;    // 16x16 thread tile, 4x4 each
    float acc[4][4] = {};
#pragma unroll 4
    for (int k = 0; k < 64; k++) {
        float a[4], b[4];
#pragma unroll
        for (int i = 0; i < 4; i++) a[i] = As[ty*4 + i][k];
#pragma unroll
        for (int j = 0; j < 4; j++) b[j] = Bs[tcc*4 + j][k];
#pragma unroll
        for (int i = 0; i < 4; i++)
#pragma unroll
            for (int j = 0; j < 4; j++) acc[i][j] += a[i]*b[j];
    }
#pragma unroll
    for (int i = 0; i < 4; i++) {
        float4 o = make_float4(acc[i][0], acc[i][1], acc[i][2], acc[i][3]);
        *(float4*)(S + (r0 + ty*4 + i)*NV + c0 + tcc*4) = o;
    }
}

// warp-per-row top-K (K includes self). grid (NV/4, 2), block 128, smem 32KB.
__global__ void k_topk2() {
    __shared__ float srow[4][NV];
    int modal = blockIdx.y;
    const float* __restrict__ S = g_sim[modal];
    int* knn = modal ? g_knn2 : g_knn1;
    const int K = modal ? 13 : 19;

    int warp = threadIdx.x >> 5, lane = threadIdx.x & 31;
    int row = blockIdx.x * 4 + warp;
    float* s = srow[warp];
    const float* Sr = S + (long)row * NV;

    for (int j = lane; j < NV; j += 32) s[j] = Sr[j];
    __syncwarp();

    int base = lane * 64;
    float bv = -1e30f; int bi = base;
#pragma unroll 8
    for (int t = 0; t < 64; t++) {
        float v = s[base + t];
        if (v > bv) { bv = v; bi = base + t; }   // strict > keeps lowest index
    }
    for (int it = 0; it < K; it++) {
        float v = bv; int idx = bi;
#pragma unroll
        for (int off = 16; off; off >>= 1) {
            float ov = __shfl_xor_sync(0xffffffffu, v, off);
            int   oi = __shfl_xor_sync(0xffffffffu, idx, off);
            if (ov > v || (ov == v && oi < idx)) { v = ov; idx = oi; }
        }
        if (lane == 0) knn[row*K + it] = idx;
        if ((idx >> 6) == lane) {
            s[idx] = -1e30f;
            bv = -1e30f; bi = base;
#pragma unroll 8
            for (int t = 0; t < 64; t++) {
                float vv = s[base + t];
                if (vv > bv) { bv = vv; bi = base + t; }
            }
        }
        __syncwarp();
    }
}

// count vertex degrees over the 4 knn edge blocks (inter edges add +1 in scan)
__global__ void k_count() {
    int idx = blockIdx.x * blockDim.x + threadIdx.x;
    if (idx >= NV*44) return;
    int j = idx / 44, t = idx % 44;
    int v;
    if      (t < 7)  v = g_knn1[j*19 + t];
    else if (t < 26) v = g_knn1[j*19 + t - 7];
    else if (t < 31) v = NV + g_knn2[j*13 + t - 26];
    else             v = NV + g_knn2[j*13 + t - 31];
    atomicAdd(&g_dv[v], 1);
}

// single-block scan of (dv+1) -> offsets; also invsqrt(DV) and counter reset
__global__ void k_scan() {
    __shared__ int part[1024];
    int tid = threadIdx.x;
    int base = tid * 4;
    int loc[4]; int s = 0;
#pragma unroll
    for (int i = 0; i < 4; i++) {
        int d = g_dv[base+i] + 1;     // +1 for the inter edge
        loc[i] = d; s += d;
        g_isdv[base+i] = rsqrtf((float)d);
        g_ctr[base+i] = 0;
    }
    part[tid] = s;
    __syncthreads();
    for (int d = 1; d < 1024; d <<= 1) {
        int t = (tid >= d) ? part[tid-d] : 0;
        __syncthreads();
        part[tid] += t;
        __syncthreads();
    }
    int run = part[tid] - s;
#pragma unroll
    for (int i = 0; i < 4; i++) { g_off[base+i] = run; run += loc[i]; }
    if (tid == 1023) g_off[VV] = part[1023];
}

// fill vertex->edge adjacency
__global__ void k_fill() {
    int idx = blockIdx.x * blockDim.x + threadIdx.x;
    if (idx >= NV*46) return;
    int v, e;
    if (idx < NV*44) {
        int j = idx / 44, t = idx % 44;
        if      (t < 7)  { v = g_knn1[j*19 + t];           e = j; }
        else if (t < 26) { v = g_knn1[j*19 + t - 7];       e = NV + j; }
        else if (t < 31) { v = NV + g_knn2[j*13 + t - 26]; e = 2*NV + j; }
        else             { v = NV + g_knn2[j*13 + t - 31]; e = 3*NV + j; }
    } else {
        int r = idx - NV*44;          // 0..2NV-1
        v = r;
        e = 4*NV + (r & (NV-1));
    }
    int slot = atomicAdd(&g_ctr[v], 1);
    g_adj[g_off[v] + slot] = e;
}

// layer-1 linear: xw[v][b*HD+o] = sum_f in[b][v][f]*W1[o][f]
__global__ void k_lin1(const float* __restrict__ f1, const float* __restrict__ f2,
                       const float* __restrict__ W) {
    __shared__ float Ws[128][65];
    __shared__ float xs[8][64];
    int o = threadIdx.x;           // 0..127
    int b = blockIdx.y;
    int v0 = blockIdx.x * 8;
    for (int i = o; i < 128*64; i += 128) Ws[i >> 6][i & 63] = W[i];
    for (int i = o; i < 8*64; i += 128) {
        int v = v0 + (i >> 6), fc = i & 63;
        xs[i >> 6][fc] = (v < NV) ? f1[(b*NV + v)*C0 + fc]
                                  : f2[(b*NV + v - NV)*C0 + fc];
    }
    __syncthreads();
#pragma unroll
    for (int vi = 0; vi < 8; vi++) {
        float acc = 0.f;
#pragma unroll
        for (int f = 0; f < 64; f++) acc += xs[vi][f] * Ws[o][f];
        g_x[(v0+vi)*CH + b*HD + o] = acc;
    }
}

// layer-2 linear: reads g_y, Fin=128 (two 64-wide halves)
__global__ void k_lin2(const float* __restrict__ W) {
    __shared__ float Ws[128][65];
    __shared__ float xs[8][64];
    int o = threadIdx.x;
    int b = blockIdx.y;
    int v0 = blockIdx.x * 8;
    float acc[8];
#pragma unroll
    for (int vi = 0; vi < 8; vi++) acc[vi] = 0.f;
    for (int half = 0; half < 2; half++) {
        __syncthreads();
        for (int i = o; i < 128*64; i += 128) {
            int r = i >> 6, fc = i & 63;
            Ws[r][fc] = W[r*128 + half*64 + fc];
        }
        for (int i = o; i < 8*64; i += 128) {
            int vi = i >> 6, fc = i & 63;
            xs[vi][fc] = g_y[(v0+vi)*CH + b*HD + half*64 + fc];
        }
        __syncthreads();
#pragma unroll
        for (int vi = 0; vi < 8; vi++) {
            float a = 0.f;
#pragma unroll
            for (int f = 0; f < 64; f++) a += xs[vi][f] * Ws[o][f];
            acc[vi] += a;
        }
    }
#pragma unroll
    for (int vi = 0; vi < 8; vi++)
        g_x[(v0+vi)*CH + b*HD + o] = acc[vi];
}

// edge gather: z[e] = (1/DE^2) * sum_{u in e} isdv[u] * x[u]
__global__ void k_edge() {
    __shared__ int   mem[19];
    __shared__ float sw[19];
    int e = blockIdx.x;
    int tid = threadIdx.x;          // 256 threads, 2 channels each
    int blk = e >> 11;
    int j = e & (NV-1);
    int cnt;
    if      (blk == 0) cnt = 7;
    else if (blk == 1) cnt = 19;
    else if (blk == 2) cnt = 5;
    else if (blk == 3) cnt = 13;
    else               cnt = 2;
    float w = 1.f / ((float)cnt * (float)cnt);
    if (tid < cnt) {
        int u;
        if      (blk <= 1) u = g_knn1[j*19 + tid];
        else if (blk <= 3) u = NV + g_knn2[j*13 + tid];
        else               u = (tid == 0) ? j : NV + j;
        mem[tid] = u;
        sw[tid] = g_isdv[u];
    }
    __syncthreads();
    float a0 = 0.f, a1 = 0.f;
    for (int t = 0; t < cnt; t++) {
        const float* xr = g_x + mem[t]*CH;
        float s = sw[t];
        a0 += xr[tid]       * s;
        a1 += xr[tid + 256] * s;
    }
    g_z[e*CH + tid]       = w * a0;
    g_z[e*CH + tid + 256] = w * a1;
}

// vertex gather + relu. mode 0 -> g_y, mode 1 -> d_out (permuted layout)
__global__ void k_vert(float* __restrict__ out, int mode) {
    int v = blockIdx.x;
    int tid = threadIdx.x;          // 256 threads, 2 channels each
    int o0 = g_off[v], o1 = g_off[v+1];
    float a0 = 0.f, a1 = 0.f;
    for (int i = o0; i < o1; i++) {
        int e = g_adj[i];
        const float* zr = g_z + e*CH;
        a0 += zr[tid];
        a1 += zr[tid + 256];
    }
    float s = g_isdv[v];
    a0 = fmaxf(a0 * s, 0.f);
    a1 = fmaxf(a1 * s, 0.f);
    if (mode == 0) {
        g_y[v*CH + tid]       = a0;
        g_y[v*CH + tid + 256] = a1;
    } else {
        int h = (v >= NV) ? 1 : 0;
        int n = v - h*NV;
        int c0 = tid, c1 = tid + 256;
        out[((h*BB + (c0 >> 7))*NV + n)*HD + (c0 & 127)] = a0;
        out[((h*BB + (c1 >> 7))*NV + n)*HD + (c1 & 127)] = a1;
    }
}

// ---------------- launch ----------------
extern "C" void kernel_launch(void* const* d_in, const int* in_sizes, int n_in,
                              void* d_out, int out_size) {
    const float* f1 = (const float*)d_in[0];
    const float* f2 = (const float*)d_in[1];
    const float* W1 = (const float*)d_in[2];
    const float* W2 = (const float*)d_in[3];
    float* out = (float*)d_out;

    k_zero<<<(VV + 255)/256, 256>>>();
    k_meannorm<<<VV, 64>>>(f1, f2);
    k_sim<<<dim3(32, 32, 2), 256>>>();
    k_topk2<<<dim3(NV/4, 2), 128>>>();
    k_count<<<(NV*44 + 255)/256, 256>>>();
    k_scan<<<1, 1024>>>();
    k_fill<<<(NV*46 + 255)/256, 256>>>();

    // layer 1
    k_lin1<<<dim3(VV/8, BB), 128>>>(f1, f2, W1);
    k_edge<<<EE, 256>>>();
    k_vert<<<VV, 256>>>(out, 0);

    // layer 2
    k_lin2<<<dim3(VV/8, BB), 128>>>(W2);
    k_edge<<<EE, 256>>>();
    k_vert<<<VV, 256>>>(out, 1);
}

// round 4
// speedup vs baseline: 3.7884x; 1.1587x over previous
#include <cuda_runtime.h>
#include <math.h>

#define NV 2048
#define VV 4096           // 2*NV
#define BB 4
#define C0 64
#define HD 128
#define EE (5*NV)         // 10240 edges
#define NNZ (46*NV)       // 94208 memberships

// ---------------- scratch (device globals; no allocation) ----------------
__device__ float g_f1[NV*C0];
__device__ float g_f2[NV*C0];
__device__ float g_sim[2][NV*NV];
__device__ int   g_knn1[NV*19];
__device__ int   g_knn2[NV*13];
__device__ int   g_dv[VV];
__device__ float g_isdv[VV];
__device__ int   g_off[VV+1];
__device__ int   g_ctr[VV];
__device__ int   g_adj[NNZ];
__device__ float g_x[VV*512];   // t (layer1 aggregate, 256ch) then u (layer2 aggregate, 512ch)
__device__ float g_z[EE*512];   // edge features
__device__ float g_y[VV*512];   // layer-1 output

__device__ __forceinline__ unsigned long long ffma2(unsigned long long a,
                                                    unsigned long long b,
                                                    unsigned long long c) {
    unsigned long long d;
    asm("fma.rn.f32x2 %0, %1, %2, %3;" : "=l"(d) : "l"(a), "l"(b), "l"(c));
    return d;
}
__device__ __forceinline__ float f2lo(unsigned long long x) {
    return __uint_as_float((unsigned)(x & 0xffffffffULL));
}
__device__ __forceinline__ float f2hi(unsigned long long x) {
    return __uint_as_float((unsigned)(x >> 32));
}

// ---------------- kernels ----------------

// batch-mean + L2-normalize rows; also zero g_dv. grid VV, block 64.
__global__ void k_meannorm(const float* __restrict__ f1, const float* __restrict__ f2) {
    int v = blockIdx.x;
    int c = threadIdx.x;
    if (c == 0) g_dv[v] = 0;
    const float* src; float* dst; int n;
    if (v < NV) { src = f1; dst = g_f1; n = v; }
    else        { src = f2; dst = g_f2; n = v - NV; }
    float m = 0.f;
#pragma unroll
    for (int b = 0; b < BB; b++) m += src[(b*NV + n)*C0 + c];
    m *= (1.0f / BB);
    __shared__ float red[64];
    red[c] = m*m;
    __syncthreads();
    for (int s = 32; s > 0; s >>= 1) {
        if (c < s) red[c] += red[c+s];
        __syncthreads();
    }
    float norm = sqrtf(red[0]);
    float d = fmaxf(norm, 1e-12f);
    dst[n*C0 + c] = m / d;
}

// sim = F F^T, 128x128 tile, K=64, packed f32x2 FMA. grid (16,16,2), block 256.
#define SIM_SMEM ((64*264 + 64*132) * 4)
__global__ void k_sim2() {
    extern __shared__ float sm[];
    float* As = sm;               // [64][264] A rows duplicated pairwise
    float* Bs = sm + 64*264;      // [64][132]
    int modal = blockIdx.z;
    const float* __restrict__ f = modal ? g_f2 : g_f1;
    float* __restrict__ S = g_sim[modal];
    int tid = threadIdx.x;
    int r0 = blockIdx.y * 128, c0 = blockIdx.x * 128;
    for (int i = tid; i < 128*64; i += 256) {
        int r = i >> 6, c = i & 63;
        float a = f[(r0 + r)*C0 + c];
        As[c*264 + 2*r]     = a;
        As[c*264 + 2*r + 1] = a;
        Bs[c*132 + r] = f[(c0 + r)*C0 + c];
    }
    __syncthreads();
    int ty = tid >> 4, tx = tid & 15;
    unsigned long long acc[8][4];
#pragma unroll
    for (int i = 0; i < 8; i++)
#pragma unroll
        for (int j = 0; j < 4; j++) acc[i][j] = 0ULL;

#pragma unroll 4
    for (int k = 0; k < 64; k++) {
        const ulonglong2* apA = (const ulonglong2*)(As + k*264 + 8*ty);
        const ulonglong2* apB = (const ulonglong2*)(As + k*264 + 128 + 8*ty);
        const ulonglong2* bpA = (const ulonglong2*)(Bs + k*132 + 4*tx);
        const ulonglong2* bpB = (const ulonglong2*)(Bs + k*132 + 64 + 4*tx);
        ulonglong2 a0 = apA[0], a1 = apA[1];
        ulonglong2 a2 = apB[0], a3 = apB[1];
        ulonglong2 b0 = bpA[0], b1 = bpB[0];
        unsigned long long av[8] = {a0.x, a0.y, a1.x, a1.y, a2.x, a2.y, a3.x, a3.y};
        unsigned long long bv[4] = {b0.x, b0.y, b1.x, b1.y};
#pragma unroll
        for (int i = 0; i < 8; i++)
#pragma unroll
            for (int j = 0; j < 4; j++)
                acc[i][j] = ffma2(av[i], bv[j], acc[i][j]);
    }
#pragma unroll
    for (int i = 0; i < 8; i++) {
        int rr = r0 + 4*ty + ((i < 4) ? i : (64 + i - 4));
        ulonglong2 s1; s1.x = acc[i][0]; s1.y = acc[i][1];
        ulonglong2 s2; s2.x = acc[i][2]; s2.y = acc[i][3];
        *(ulonglong2*)(S + (size_t)rr*NV + c0 + 4*tx)      = s1;
        *(ulonglong2*)(S + (size_t)rr*NV + c0 + 64 + 4*tx) = s2;
    }
}

#define TK_INSERT(v, idx)                                          \
    if ((v) > v3) {                                                \
        if ((v) > v2) {                                            \
            v3 = v2; i3 = i2;                                      \
            if ((v) > v1) {                                        \
                v2 = v1; i2 = i1;                                  \
                if ((v) > v0) { v1 = v0; i1 = i0; v0 = (v); i0 = (idx); } \
                else { v1 = (v); i1 = (idx); }                     \
            } else { v2 = (v); i2 = (idx); }                       \
        } else { v3 = (v); i3 = (idx); }                           \
    }

// warp-per-row top-K with per-lane top-4 cache; fused degree counting.
// grid (NV/4, 2), block 128.
__global__ void k_topk3() {
    __shared__ float srow[4][NV];
    int modal = blockIdx.y;
    const float* __restrict__ S = g_sim[modal];
    int* knn = modal ? g_knn2 : g_knn1;
    const int K  = modal ? 13 : 19;
    const int kp = modal ? 5 : 7;       // first kp entries belong to 2 edges
    int warp = threadIdx.x >> 5, lane = threadIdx.x & 31;
    int row = blockIdx.x * 4 + warp;
    float* s = srow[warp];
    int base = lane * 64;
    float v0 = -1e30f, v1 = -1e30f, v2 = -1e30f, v3 = -1e30f;
    int i0 = base, i1 = base, i2 = base, i3 = base;
    {
        const float4* Sr4 = (const float4*)(S + (size_t)row * NV);
#pragma unroll 4
        for (int t = 0; t < 16; t++) {
            float4 x = Sr4[lane*16 + t];
            ((float4*)s)[lane*16 + t] = x;
            int idx = base + t*4;
            TK_INSERT(x.x, idx);
            TK_INSERT(x.y, idx+1);
            TK_INSERT(x.z, idx+2);
            TK_INSERT(x.w, idx+3);
        }
    }
    __syncwarp();
    for (int it = 0; it < K; it++) {
        float m = v0;
#pragma unroll
        for (int off = 16; off; off >>= 1)
            m = fmaxf(m, __shfl_xor_sync(0xffffffffu, m, off));
        unsigned msk = __ballot_sync(0xffffffffu, v0 == m);
        int src = __ffs(msk) - 1;
        int widx = __shfl_sync(0xffffffffu, i0, src);
        if (lane == 0) {
            knn[row*K + it] = widx;
            int vtx = modal ? (NV + widx) : widx;
            atomicAdd(&g_dv[vtx], (it < kp) ? 2 : 1);
        }
        if (lane == src) {
            s[i0] = -1e30f;
            v0 = v1; i0 = i1; v1 = v2; i1 = i2; v2 = v3; i2 = i3;
            v3 = -1e30f; i3 = base;
            if (v0 == -1e30f) {     // cache exhausted: rescan segment
                v0 = v1 = v2 = v3 = -1e30f;
                i0 = i1 = i2 = i3 = base;
#pragma unroll 4
                for (int t = 0; t < 64; t++) {
                    float v = s[base + t];
                    TK_INSERT(v, base + t);
                }
            }
        }
        __syncwarp();
    }
}

// single-block scan of (dv+1) -> offsets; also invsqrt(DV) and counter reset
__global__ void k_scan() {
    __shared__ int part[1024];
    int tid = threadIdx.x;
    int base = tid * 4;
    int loc[4]; int s = 0;
#pragma unroll
    for (int i = 0; i < 4; i++) {
        int d = g_dv[base+i] + 1;     // +1 for the inter edge
        loc[i] = d; s += d;
        g_isdv[base+i] = rsqrtf((float)d);
        g_ctr[base+i] = 0;
    }
    part[tid] = s;
    __syncthreads();
    for (int d = 1; d < 1024; d <<= 1) {
        int t = (tid >= d) ? part[tid-d] : 0;
        __syncthreads();
        part[tid] += t;
        __syncthreads();
    }
    int run = part[tid] - s;
#pragma unroll
    for (int i = 0; i < 4; i++) { g_off[base+i] = run; run += loc[i]; }
    if (tid == 1023) g_off[VV] = part[1023];
}

// fill vertex->edge adjacency
__global__ void k_fill() {
    int idx = blockIdx.x * blockDim.x + threadIdx.x;
    if (idx >= NV*46) return;
    int v, e;
    if (idx < NV*44) {
        int j = idx / 44, t = idx % 44;
        if      (t < 7)  { v = g_knn1[j*19 + t];           e = j; }
        else if (t < 26) { v = g_knn1[j*19 + t - 7];       e = NV + j; }
        else if (t < 31) { v = NV + g_knn2[j*13 + t - 26]; e = 2*NV + j; }
        else             { v = NV + g_knn2[j*13 + t - 31]; e = 3*NV + j; }
    } else {
        int r = idx - NV*44;          // 0..2NV-1
        v = r;
        e = 4*NV + (r & (NV-1));
    }
    int slot = atomicAdd(&g_ctr[v], 1);
    g_adj[g_off[v] + slot] = e;
}

// edge membership decode helper (cnt, members into smem)
__device__ __forceinline__ int edge_members(int e, int tid, int* mem, float* sw, float* w) {
    int blk = e >> 11;
    int j = e & (NV-1);
    int cnt;
    if      (blk == 0) cnt = 7;
    else if (blk == 1) cnt = 19;
    else if (blk == 2) cnt = 5;
    else if (blk == 3) cnt = 13;
    else               cnt = 2;
    *w = 1.f / ((float)cnt * (float)cnt);
    if (tid < cnt) {
        int u;
        if      (blk <= 1) u = g_knn1[j*19 + tid];
        else if (blk <= 3) u = NV + g_knn2[j*13 + tid];
        else               u = (tid == 0) ? j : NV + j;
        mem[tid] = u;
        sw[tid] = g_isdv[u];
    }
    return cnt;
}

// layer-1 edge gather over RAW inputs (256 ch). grid EE, block 256.
__global__ void k_edge1(const float* __restrict__ f1, const float* __restrict__ f2) {
    __shared__ int   mem[19];
    __shared__ float sw[19];
    int e = blockIdx.x;
    int tid = threadIdx.x;            // ch = b*64+c
    float w;
    int cnt = edge_members(e, tid, mem, sw, &w);
    __syncthreads();
    int b = tid >> 6, c = tid & 63;
    float a = 0.f;
    for (int t = 0; t < cnt; t++) {
        int u = mem[t];
        float s = sw[t];
        float val = (u < NV) ? f1[(b*NV + u)*C0 + c]
                             : f2[(b*NV + u - NV)*C0 + c];
        a += val * s;
    }
    g_z[e*256 + tid] = w * a;
}

// layer-1 vertex gather (256 ch), no relu. grid VV, block 256.
__global__ void k_vert1() {
    int v = blockIdx.x;
    int tid = threadIdx.x;
    int o0 = g_off[v], o1 = g_off[v+1];
    float a = 0.f;
    for (int i = o0; i < o1; i++)
        a += g_z[g_adj[i]*256 + tid];
    g_x[v*256 + tid] = g_isdv[v] * a;
}

// layer-1 linear + relu: y[v][b*128+o] = relu(sum_c t[v][b*64+c]*W1[o][c])
// grid (VV/8, BB), block 128. packed f32x2.
__global__ void k_lin1n(const float* __restrict__ W) {
    __shared__ float Ws[128*66];
    __shared__ float xs[8*66];
    int o = threadIdx.x;
    int b = blockIdx.y;
    int v0 = blockIdx.x * 8;
    for (int i = o; i < 128*64; i += 128) {
        int r = i >> 6, c = i & 63;
        Ws[r*66 + c] = W[i];
    }
    for (int i = o; i < 8*64; i += 128) {
        int vi = i >> 6, c = i & 63;
        xs[vi*66 + c] = g_x[(v0+vi)*256 + b*64 + c];
    }
    __syncthreads();
    unsigned long long acc[8];
#pragma unroll
    for (int vi = 0; vi < 8; vi++) acc[vi] = 0ULL;
#pragma unroll 8
    for (int fp = 0; fp < 32; fp++) {
        unsigned long long w = *(const unsigned long long*)(Ws + o*66 + 2*fp);
#pragma unroll
        for (int vi = 0; vi < 8; vi++)
            acc[vi] = ffma2(*(const unsigned long long*)(xs + vi*66 + 2*fp), w, acc[vi]);
    }
#pragma unroll
    for (int vi = 0; vi < 8; vi++) {
        float y = fmaxf(f2lo(acc[vi]) + f2hi(acc[vi]), 0.f);
        g_y[(v0+vi)*512 + b*HD + o] = y;
    }
}

// layer-2 edge gather over g_y (512 ch). grid EE, block 256, 2 ch each.
__global__ void k_edge2() {
    __shared__ int   mem[19];
    __shared__ float sw[19];
    int e = blockIdx.x;
    int tid = threadIdx.x;
    float w;
    int cnt = edge_members(e, tid, mem, sw, &w);
    __syncthreads();
    float a0 = 0.f, a1 = 0.f;
    for (int t = 0; t < cnt; t++) {
        const float* yr = g_y + mem[t]*512;
        float s = sw[t];
        a0 += yr[tid]       * s;
        a1 += yr[tid + 256] * s;
    }
    g_z[e*512 + tid]       = w * a0;
    g_z[e*512 + tid + 256] = w * a1;
}

// layer-2 vertex gather (512 ch), no relu. grid VV, block 256, 2 ch each.
__global__ void k_vert2() {
    int v = blockIdx.x;
    int tid = threadIdx.x;
    int o0 = g_off[v], o1 = g_off[v+1];
    float a0 = 0.f, a1 = 0.f;
    for (int i = o0; i < o1; i++) {
        const float* zr = g_z + g_adj[i]*512;
        a0 += zr[tid];
        a1 += zr[tid + 256];
    }
    float s = g_isdv[v];
    g_x[v*512 + tid]       = s * a0;
    g_x[v*512 + tid + 256] = s * a1;
}

// layer-2 linear + relu + permuted store. grid (VV/8, BB), block 128.
__global__ void k_lin2n(const float* __restrict__ W, float* __restrict__ out) {
    __shared__ float Ws[128*66];
    __shared__ float xs[8*132];
    int o = threadIdx.x;
    int b = blockIdx.y;
    int v0 = blockIdx.x * 8;
    for (int i = o; i < 8*128; i += 128) {
        int vi = i >> 7, c = i & 127;
        xs[vi*132 + c] = g_x[(v0+vi)*512 + b*HD + c];
    }
    unsigned long long acc[8];
#pragma unroll
    for (int vi = 0; vi < 8; vi++) acc[vi] = 0ULL;
    for (int half = 0; half < 2; half++) {
        __syncthreads();
        for (int i = o; i < 128*64; i += 128) {
            int r = i >> 6, c = i & 63;
            Ws[r*66 + c] = W[r*HD + half*64 + c];
        }
        __syncthreads();
#pragma unroll 8
        for (int fp = 0; fp < 32; fp++) {
            unsigned long long w = *(const unsigned long long*)(Ws + o*66 + 2*fp);
#pragma unroll
            for (int vi = 0; vi < 8; vi++)
                acc[vi] = ffma2(*(const unsigned long long*)(xs + vi*132 + half*64 + 2*fp), w, acc[vi]);
        }
    }
#pragma unroll
    for (int vi = 0; vi < 8; vi++) {
        float y = fmaxf(f2lo(acc[vi]) + f2hi(acc[vi]), 0.f);
        int v = v0 + vi;
        int h = (v >= NV) ? 1 : 0;
        int n = v - h*NV;
        out[((h*BB + b)*NV + n)*HD + o] = y;
    }
}

// ---------------- launch ----------------
extern "C" void kernel_launch(void* const* d_in, const int* in_sizes, int n_in,
                              void* d_out, int out_size) {
    const float* f1 = (const float*)d_in[0];
    const float* f2 = (const float*)d_in[1];
    const float* W1 = (const float*)d_in[2];
    const float* W2 = (const float*)d_in[3];
    float* out = (float*)d_out;

    cudaFuncSetAttribute(k_sim2, cudaFuncAttributeMaxDynamicSharedMemorySize, SIM_SMEM);

    k_meannorm<<<VV, 64>>>(f1, f2);
    k_sim2<<<dim3(16, 16, 2), 256, SIM_SMEM>>>();
    k_topk3<<<dim3(NV/4, 2), 128>>>();
    k_scan<<<1, 1024>>>();
    k_fill<<<(NV*46 + 255)/256, 256>>>();

    // layer 1:  relu((A x) W1)
    k_edge1<<<EE, 256>>>(f1, f2);
    k_vert1<<<VV, 256>>>();
    k_lin1n<<<dim3(VV/8, BB), 128>>>(W1);

    // layer 2:  relu((A y) W2)
    k_edge2<<<EE, 256>>>();
    k_vert2<<<VV, 256>>>();
    k_lin2n<<<dim3(VV/8, BB), 128>>>(W2, out);
}

// round 6
// speedup vs baseline: 4.4231x; 1.1675x over previous
#include <cuda_runtime.h>
#include <cuda_fp16.h>
#include <math.h>

#define NV 2048
#define VV 4096           // 2*NV
#define BB 4
#define C0 64
#define HD 128
#define EE (5*NV)         // 10240 edges
#define NNZ (46*NV)       // 94208 memberships

// ---------------- scratch (device globals; no allocation) ----------------
__device__ float  g_f1[NV*C0];
__device__ float  g_f2[NV*C0];
__device__ float  g_sim[2][NV*NV];
__device__ int    g_knn1[NV*19];
__device__ int    g_knn2[NV*13];
__device__ int    g_dv[VV];
__device__ float  g_isdv[VV];
__device__ int    g_off[VV+1];
__device__ int    g_ctr[VV];
__device__ int    g_adj[NNZ];
__device__ float  g_t[VV*256];    // layer-1 aggregate (fp32)
__device__ float  g_u[VV*512];    // layer-2 aggregate (fp32)
__device__ __half g_yh[VV*512];   // layer-1 output (half)
__device__ __half g_z1h[EE*256];  // layer-1 edge features (half)
__device__ __half g_z2h[EE*512];  // layer-2 edge features (half)

__device__ __forceinline__ unsigned long long ffma2(unsigned long long a,
                                                    unsigned long long b,
                                                    unsigned long long c) {
    unsigned long long d;
    asm("fma.rn.f32x2 %0, %1, %2, %3;" : "=l"(d) : "l"(a), "l"(b), "l"(c));
    return d;
}
__device__ __forceinline__ float f2lo(unsigned long long x) {
    return __uint_as_float((unsigned)(x & 0xffffffffULL));
}
__device__ __forceinline__ float f2hi(unsigned long long x) {
    return __uint_as_float((unsigned)(x >> 32));
}
__device__ __forceinline__ float4 h4_to_f4(uint2 p) {
    __half2 h0 = *(__half2*)&p.x, h1 = *(__half2*)&p.y;
    float2 f0 = __half22float2(h0), f1 = __half22float2(h1);
    return make_float4(f0.x, f0.y, f1.x, f1.y);
}

// ---------------- kernels ----------------

// batch-mean + L2-normalize rows; also zero g_dv. grid VV, block 64.
__global__ void k_meannorm(const float* __restrict__ f1, const float* __restrict__ f2) {
    int v = blockIdx.x;
    int c = threadIdx.x;
    if (c == 0) g_dv[v] = 0;
    const float* src; float* dst; int n;
    if (v < NV) { src = f1; dst = g_f1; n = v; }
    else        { src = f2; dst = g_f2; n = v - NV; }
    float m = 0.f;
#pragma unroll
    for (int b = 0; b < BB; b++) m += src[(b*NV + n)*C0 + c];
    m *= (1.0f / BB);
    __shared__ float red[64];
    red[c] = m*m;
    __syncthreads();
    for (int s = 32; s > 0; s >>= 1) {
        if (c < s) red[c] += red[c+s];
        __syncthreads();
    }
    float norm = sqrtf(red[0]);
    float d = fmaxf(norm, 1e-12f);
    dst[n*C0 + c] = m / d;
}

// sim = F F^T, 128x128 tile, K=64, packed f32x2 FMA. grid (16,16,2), block 256.
#define SIM_SMEM ((64*264 + 64*132) * 4)
__global__ void k_sim2() {
    extern __shared__ float sm[];
    float* As = sm;               // [64][264] A rows duplicated pairwise
    float* Bs = sm + 64*264;      // [64][132]
    int modal = blockIdx.z;
    const float* __restrict__ f = modal ? g_f2 : g_f1;
    float* __restrict__ S = g_sim[modal];
    int tid = threadIdx.x;
    int r0 = blockIdx.y * 128, c0 = blockIdx.x * 128;
    for (int i = tid; i < 128*64; i += 256) {
        int r = i >> 6, c = i & 63;
        float a = f[(r0 + r)*C0 + c];
        As[c*264 + 2*r]     = a;
        As[c*264 + 2*r + 1] = a;
        Bs[c*132 + r] = f[(c0 + r)*C0 + c];
    }
    __syncthreads();
    int ty = tid >> 4, tx = tid & 15;
    unsigned long long acc[8][4];
#pragma unroll
    for (int i = 0; i < 8; i++)
#pragma unroll
        for (int j = 0; j < 4; j++) acc[i][j] = 0ULL;

#pragma unroll 4
    for (int k = 0; k < 64; k++) {
        const ulonglong2* apA = (const ulonglong2*)(As + k*264 + 8*ty);
        const ulonglong2* apB = (const ulonglong2*)(As + k*264 + 128 + 8*ty);
        const ulonglong2* bpA = (const ulonglong2*)(Bs + k*132 + 4*tx);
        const ulonglong2* bpB = (const ulonglong2*)(Bs + k*132 + 64 + 4*tx);
        ulonglong2 a0 = apA[0], a1 = apA[1];
        ulonglong2 a2 = apB[0], a3 = apB[1];
        ulonglong2 b0 = bpA[0], b1 = bpB[0];
        unsigned long long av[8] = {a0.x, a0.y, a1.x, a1.y, a2.x, a2.y, a3.x, a3.y};
        unsigned long long bv[4] = {b0.x, b0.y, b1.x, b1.y};
#pragma unroll
        for (int i = 0; i < 8; i++)
#pragma unroll
            for (int j = 0; j < 4; j++)
                acc[i][j] = ffma2(av[i], bv[j], acc[i][j]);
    }
#pragma unroll
    for (int i = 0; i < 8; i++) {
        int rr = r0 + 4*ty + ((i < 4) ? i : (64 + i - 4));
        ulonglong2 s1; s1.x = acc[i][0]; s1.y = acc[i][1];
        ulonglong2 s2; s2.x = acc[i][2]; s2.y = acc[i][3];
        *(ulonglong2*)(S + (size_t)rr*NV + c0 + 4*tx)      = s1;
        *(ulonglong2*)(S + (size_t)rr*NV + c0 + 64 + 4*tx) = s2;
    }
}

#define TK_INSERT(v, idx)                                          \
    if ((v) > v3) {                                                \
        if ((v) > v2) {                                            \
            v3 = v2; i3 = i2;                                      \
            if ((v) > v1) {                                        \
                v2 = v1; i2 = i1;                                  \
                if ((v) > v0) { v1 = v0; i1 = i0; v0 = (v); i0 = (idx); } \
                else { v1 = (v); i1 = (idx); }                     \
            } else { v2 = (v); i2 = (idx); }                       \
        } else { v3 = (v); i3 = (idx); }                           \
    }

// warp-per-row top-K with per-lane top-4 cache; fused degree counting.
// grid (NV/4, 2), block 128.
__global__ void k_topk3() {
    __shared__ float srow[4][NV];
    int modal = blockIdx.y;
    const float* __restrict__ S = g_sim[modal];
    int* knn = modal ? g_knn2 : g_knn1;
    const int K  = modal ? 13 : 19;
    const int kp = modal ? 5 : 7;       // first kp entries belong to 2 edges
    int warp = threadIdx.x >> 5, lane = threadIdx.x & 31;
    int row = blockIdx.x * 4 + warp;
    float* s = srow[warp];
    int base = lane * 64;
    float v0 = -1e30f, v1 = -1e30f, v2 = -1e30f, v3 = -1e30f;
    int i0 = base, i1 = base, i2 = base, i3 = base;
    {
        const float4* Sr4 = (const float4*)(S + (size_t)row * NV);
#pragma unroll 4
        for (int t = 0; t < 16; t++) {
            float4 x = Sr4[lane*16 + t];
            ((float4*)s)[lane*16 + t] = x;
            int idx = base + t*4;
            TK_INSERT(x.x, idx);
            TK_INSERT(x.y, idx+1);
            TK_INSERT(x.z, idx+2);
            TK_INSERT(x.w, idx+3);
        }
    }
    __syncwarp();
    for (int it = 0; it < K; it++) {
        float m = v0;
#pragma unroll
        for (int off = 16; off; off >>= 1)
            m = fmaxf(m, __shfl_xor_sync(0xffffffffu, m, off));
        unsigned msk = __ballot_sync(0xffffffffu, v0 == m);
        int src = __ffs(msk) - 1;
        int widx = __shfl_sync(0xffffffffu, i0, src);
        if (lane == 0) {
            knn[row*K + it] = widx;
            int vtx = modal ? (NV + widx) : widx;
            atomicAdd(&g_dv[vtx], (it < kp) ? 2 : 1);
        }
        if (lane == src) {
            s[i0] = -1e30f;
            v0 = v1; i0 = i1; v1 = v2; i1 = i2; v2 = v3; i2 = i3;
            v3 = -1e30f; i3 = base;
            if (v0 == -1e30f) {     // cache exhausted: rescan segment
                v0 = v1 = v2 = v3 = -1e30f;
                i0 = i1 = i2 = i3 = base;
#pragma unroll 4
                for (int t = 0; t < 64; t++) {
                    float v = s[base + t];
                    TK_INSERT(v, base + t);
                }
            }
        }
        __syncwarp();
    }
}

// single-block shuffle scan of (dv+1) -> offsets; invsqrt(DV); counter reset
__global__ void k_scan2() {
    __shared__ int wsum[32];
    int tid = threadIdx.x;                 // 1024 threads x 4 elems
    int warp = tid >> 5, lane = tid & 31;
    int base = tid * 4;
    int loc[4]; int s = 0;
#pragma unroll
    for (int i = 0; i < 4; i++) {
        int d = g_dv[base+i] + 1;          // +1 for the inter edge
        loc[i] = d; s += d;
        g_isdv[base+i] = rsqrtf((float)d);
        g_ctr[base+i] = 0;
    }
    int incl = s;
#pragma unroll
    for (int off = 1; off < 32; off <<= 1) {
        int o = __shfl_up_sync(0xffffffffu, incl, off);
        if (lane >= off) incl += o;
    }
    if (lane == 31) wsum[warp] = incl;
    __syncthreads();
    if (warp == 0) {
        int w = wsum[lane];
#pragma unroll
        for (int off = 1; off < 32; off <<= 1) {
            int o = __shfl_up_sync(0xffffffffu, w, off);
            if (lane >= off) w += o;
        }
        wsum[lane] = w;
    }
    __syncthreads();
    int run = (warp ? wsum[warp-1] : 0) + incl - s;
#pragma unroll
    for (int i = 0; i < 4; i++) { g_off[base+i] = run; run += loc[i]; }
    if (tid == 1023) g_off[VV] = wsum[31];
}

// fill vertex->edge adjacency
__global__ void k_fill() {
    int idx = blockIdx.x * blockDim.x + threadIdx.x;
    if (idx >= NV*46) return;
    int v, e;
    if (idx < NV*44) {
        int j = idx / 44, t = idx % 44;
        if      (t < 7)  { v = g_knn1[j*19 + t];           e = j; }
        else if (t < 26) { v = g_knn1[j*19 + t - 7];       e = NV + j; }
        else if (t < 31) { v = NV + g_knn2[j*13 + t - 26]; e = 2*NV + j; }
        else             { v = NV + g_knn2[j*13 + t - 31]; e = 3*NV + j; }
    } else {
        int r = idx - NV*44;          // 0..2NV-1
        v = r;
        e = 4*NV + (r & (NV-1));
    }
    int slot = atomicAdd(&g_ctr[v], 1);
    g_adj[g_off[v] + slot] = e;
}

// edge membership decode helper (cnt, members into smem)
__device__ __forceinline__ int edge_members(int e, int tid, int* mem, float* sw, float* w) {
    int blk = e >> 11;
    int j = e & (NV-1);
    int cnt;
    if      (blk == 0) cnt = 7;
    else if (blk == 1) cnt = 19;
    else if (blk == 2) cnt = 5;
    else if (blk == 3) cnt = 13;
    else               cnt = 2;
    *w = 1.f / ((float)cnt * (float)cnt);
    if (tid < cnt) {
        int u;
        if      (blk <= 1) u = g_knn1[j*19 + tid];
        else if (blk <= 3) u = NV + g_knn2[j*13 + tid];
        else               u = (tid == 0) ? j : NV + j;
        mem[tid] = u;
        sw[tid] = g_isdv[u];
    }
    return cnt;
}

// layer-1 edge gather over RAW inputs (256 ch). grid EE, block 128, 2 ch each.
__global__ void k_edge1(const float* __restrict__ f1, const float* __restrict__ f2) {
    __shared__ int   mem[19];
    __shared__ float sw[19];
    int e = blockIdx.x;
    int tid = threadIdx.x;
    float w;
    int cnt = edge_members(e, tid, mem, sw, &w);
    __syncthreads();
    int ch = 2*tid, b = ch >> 6, c = ch & 63;
    float a0 = 0.f, a1 = 0.f;
    for (int t = 0; t < cnt; t++) {
        int u = mem[t];
        float s = sw[t];
        float2 val = (u < NV) ? *(const float2*)(f1 + (b*NV + u)*C0 + c)
                              : *(const float2*)(f2 + (b*NV + u - NV)*C0 + c);
        a0 += val.x * s;
        a1 += val.y * s;
    }
    *(__half2*)(g_z1h + e*256 + ch) = __floats2half2_rn(w*a0, w*a1);
}

// layer-1 vertex gather (256 ch). grid VV, block 128, 2 ch each.
__global__ void k_vert1() {
    int v = blockIdx.x;
    int tid = threadIdx.x;
    int o0 = g_off[v], o1 = g_off[v+1];
    float a0 = 0.f, a1 = 0.f;
    int i = o0;
    for (; i + 2 <= o1; i += 2) {
        __half2 p0 = *(const __half2*)(g_z1h + g_adj[i]*256   + 2*tid);
        __half2 p1 = *(const __half2*)(g_z1h + g_adj[i+1]*256 + 2*tid);
        float2 q0 = __half22float2(p0), q1 = __half22float2(p1);
        a0 += q0.x + q1.x;
        a1 += q0.y + q1.y;
    }
    if (i < o1) {
        float2 q = __half22float2(*(const __half2*)(g_z1h + g_adj[i]*256 + 2*tid));
        a0 += q.x; a1 += q.y;
    }
    float s = g_isdv[v];
    *(float2*)(g_t + v*256 + 2*tid) = make_float2(s*a0, s*a1);
}

// layer-1 linear + relu: yh[v][b*128+o] = relu(sum_c t[v][b*64+c]*W1[o][c])
// grid (VV/16, BB), block 128. packed f32x2. output half.
__global__ void k_lin1n(const float* __restrict__ W) {
    __shared__ float Ws[128*66];
    __shared__ float xs[16*66];
    int o = threadIdx.x;
    int b = blockIdx.y;
    int v0 = blockIdx.x * 16;
    for (int i = o; i < 128*64; i += 128) {
        int r = i >> 6, c = i & 63;
        Ws[r*66 + c] = W[i];
    }
    for (int i = o; i < 16*64; i += 128) {
        int vi = i >> 6, c = i & 63;
        xs[vi*66 + c] = g_t[(v0+vi)*256 + b*64 + c];
    }
    __syncthreads();
    unsigned long long acc[16];
#pragma unroll
    for (int vi = 0; vi < 16; vi++) acc[vi] = 0ULL;
#pragma unroll 4
    for (int fp = 0; fp < 32; fp++) {
        unsigned long long w = *(const unsigned long long*)(Ws + o*66 + 2*fp);
#pragma unroll
        for (int vi = 0; vi < 16; vi++)
            acc[vi] = ffma2(*(const unsigned long long*)(xs + vi*66 + 2*fp), w, acc[vi]);
    }
#pragma unroll
    for (int vi = 0; vi < 16; vi++) {
        float y = fmaxf(f2lo(acc[vi]) + f2hi(acc[vi]), 0.f);
        g_yh[(v0+vi)*512 + b*HD + o] = __float2half(y);
    }
}

// layer-2 edge gather over g_yh (512 ch). grid EE, block 128, 4 ch each.
__global__ void k_edge2() {
    __shared__ int   mem[19];
    __shared__ float sw[19];
    int e = blockIdx.x;
    int tid = threadIdx.x;
    float w;
    int cnt = edge_members(e, tid, mem, sw, &w);
    __syncthreads();
    float a0 = 0.f, a1 = 0.f, a2 = 0.f, a3 = 0.f;
    for (int t = 0; t < cnt; t++) {
        float s = sw[t];
        float4 f = h4_to_f4(*(const uint2*)(g_yh + mem[t]*512 + 4*tid));
        a0 += f.x*s; a1 += f.y*s; a2 += f.z*s; a3 += f.w*s;
    }
    __half2 r0 = __floats2half2_rn(w*a0, w*a1);
    __half2 r1 = __floats2half2_rn(w*a2, w*a3);
    uint2 o; o.x = *(unsigned*)&r0; o.y = *(unsigned*)&r1;
    *(uint2*)(g_z2h + e*512 + 4*tid) = o;
}

// layer-2 vertex gather (512 ch). grid VV, block 128, 4 ch each.
__global__ void k_vert2() {
    int v = blockIdx.x;
    int tid = threadIdx.x;
    int o0 = g_off[v], o1 = g_off[v+1];
    float a0 = 0.f, a1 = 0.f, a2 = 0.f, a3 = 0.f;
    int i = o0;
    for (; i + 2 <= o1; i += 2) {
        float4 f = h4_to_f4(*(const uint2*)(g_z2h + g_adj[i]*512   + 4*tid));
        float4 g = h4_to_f4(*(const uint2*)(g_z2h + g_adj[i+1]*512 + 4*tid));
        a0 += f.x + g.x; a1 += f.y + g.y; a2 += f.z + g.z; a3 += f.w + g.w;
    }
    if (i < o1) {
        float4 f = h4_to_f4(*(const uint2*)(g_z2h + g_adj[i]*512 + 4*tid));
        a0 += f.x; a1 += f.y; a2 += f.z; a3 += f.w;
    }
    float s = g_isdv[v];
    *(float4*)(g_u + v*512 + 4*tid) = make_float4(s*a0, s*a1, s*a2, s*a3);
}

// layer-2 linear + relu + permuted store. grid (VV/16, BB), block 128.
__global__ void k_lin2n(const float* __restrict__ W, float* __restrict__ out) {
    __shared__ float Ws[128*66];
    __shared__ float xs[16*132];
    int o = threadIdx.x;
    int b = blockIdx.y;
    int v0 = blockIdx.x * 16;
    for (int i = o; i < 16*128; i += 128) {
        int vi = i >> 7, c = i & 127;
        xs[vi*132 + c] = g_u[(v0+vi)*512 + b*HD + c];
    }
    unsigned long long acc[16];
#pragma unroll
    for (int vi = 0; vi < 16; vi++) acc[vi] = 0ULL;
    for (int half = 0; half < 2; half++) {
        __syncthreads();
        for (int i = o; i < 128*64; i += 128) {
            int r = i >> 6, c = i & 63;
            Ws[r*66 + c] = W[r*HD + half*64 + c];
        }
        __syncthreads();
#pragma unroll 4
        for (int fp = 0; fp < 32; fp++) {
            unsigned long long w = *(const unsigned long long*)(Ws + o*66 + 2*fp);
#pragma unroll
            for (int vi = 0; vi < 16; vi++)
                acc[vi] = ffma2(*(const unsigned long long*)(xs + vi*132 + half*64 + 2*fp), w, acc[vi]);
        }
    }
#pragma unroll
    for (int vi = 0; vi < 16; vi++) {
        float y = fmaxf(f2lo(acc[vi]) + f2hi(acc[vi]), 0.f);
        int v = v0 + vi;
        int h = (v >= NV) ? 1 : 0;
        int n = v - h*NV;
        out[((h*BB + b)*NV + n)*HD + o] = y;
    }
}

// ---------------- launch ----------------
extern "C" void kernel_launch(void* const* d_in, const int* in_sizes, int n_in,
                              void* d_out, int out_size) {
    const float* f1 = (const float*)d_in[0];
    const float* f2 = (const float*)d_in[1];
    const float* W1 = (const float*)d_in[2];
    const float* W2 = (const float*)d_in[3];
    float* out = (float*)d_out;

    cudaFuncSetAttribute(k_sim2, cudaFuncAttributeMaxDynamicSharedMemorySize, SIM_SMEM);

    k_meannorm<<<VV, 64>>>(f1, f2);
    k_sim2<<<dim3(16, 16, 2), 256, SIM_SMEM>>>();
    k_topk3<<<dim3(NV/4, 2), 128>>>();
    k_scan2<<<1, 1024>>>();
    k_fill<<<(NV*46 + 255)/256, 256>>>();

    // layer 1:  relu((A x) W1)
    k_edge1<<<EE, 128>>>(f1, f2);
    k_vert1<<<VV, 128>>>();
    k_lin1n<<<dim3(VV/16, BB), 128>>>(W1);

    // layer 2:  relu((A y) W2)
    k_edge2<<<EE, 128>>>();
    k_vert2<<<VV, 128>>>();
    k_lin2n<<<dim3(VV/16, BB), 128>>>(W2, out);
}